// round 5
// baseline (speedup 1.0000x reference)
#include <cuda_runtime.h>
#include <stdint.h>

// MergedEmbSGD: merged multi-table EmbeddingBag, sum pooling.
// weights: [T, N, D] fp32 ; indices/offsets int32 or int64 (runtime-detected
// in-kernel: offsets per table = [0, L, 2L, ...]; int32 view of an int64
// buffer has elem 1 == 0, genuine int32 has elem 1 == L != 0).
// out: [T, B, D] fp32.
// Persistent grid; each warp processes a PAIR of consecutive bags per
// iteration (same table since B is even): 8 gather loads in flight, 1KB
// contiguous streaming store burst.

#define D_DIM 128
#define D_VEC (D_DIM / 4)   // 32 float4 per row == one per lane

__device__ __forceinline__ void store_cs(float4* p, float4 v)
{
    asm volatile("st.global.cs.v4.f32 [%0], {%1,%2,%3,%4};"
                 :: "l"(p), "f"(v.x), "f"(v.y), "f"(v.z), "f"(v.w) : "memory");
}

// Load 4 consecutive indices starting at s (caller guarantees s % 4 == 0).
__device__ __forceinline__ void load4idx(const int* p, long long s,
                                         long long& r0, long long& r1,
                                         long long& r2, long long& r3)
{
    int4 v = __ldg((const int4*)(p + s));
    r0 = v.x; r1 = v.y; r2 = v.z; r3 = v.w;
}
__device__ __forceinline__ void load4idx(const long long* p, long long s,
                                         long long& r0, long long& r1,
                                         long long& r2, long long& r3)
{
    longlong2 a = __ldg((const longlong2*)(p + s));
    longlong2 b = __ldg((const longlong2*)(p + s + 2));
    r0 = a.x; r1 = a.y; r2 = b.x; r3 = b.y;
}

template <typename IT>
__device__ __forceinline__ float4 pool_general(
    const float4* __restrict__ w_t, const IT* __restrict__ idx_t,
    long long start, long long end, int lane)
{
    float4 acc; acc.x = 0.f; acc.y = 0.f; acc.z = 0.f; acc.w = 0.f;
    for (long long i = start; i < end; ++i) {
        const long long r = (long long)idx_t[i];
        const float4 v = __ldg(w_t + r * D_VEC + lane);
        acc.x += v.x; acc.y += v.y; acc.z += v.z; acc.w += v.w;
    }
    return acc;
}

template <typename IT>
__device__ __forceinline__ void run_pairs(
    const float4* __restrict__ w,
    const IT* __restrict__ idx,
    const IT* __restrict__ offs,
    float4* __restrict__ out,
    int T, long long N, int B, int bshift, int BL, int total_bags,
    int warp, int nwarps, int lane)
{
    const long long wstride = N * D_VEC;
    const int total_pairs = total_bags >> 1;   // B even -> pairs never straddle tables

    for (int pair = warp; pair < total_pairs; pair += nwarps) {
        const int bag0 = pair << 1;
        const int t = (bshift >= 0) ? (bag0 >> bshift) : (bag0 / B);
        const int b = bag0 - t * B;

        const IT* __restrict__ offs_t = offs + (long long)t * B;
        const long long s0 = (long long)offs_t[b];
        const long long s1 = (long long)offs_t[b + 1];
        const long long e1 = (b + 2 < B) ? (long long)offs_t[b + 2]
                                         : (long long)BL;

        const IT*     __restrict__ idx_t = idx + (long long)t * BL;
        const float4* __restrict__ w_t   = w + (long long)t * wstride;

        float4 a0, a1;

        if ((s1 - s0) == 4 && (e1 - s1) == 4 && ((s0 & 3) == 0)) {
            // Fast path: both bags length 4, 8 consecutive indices.
            long long r0, r1, r2, r3, r4, r5, r6, r7;
            load4idx(idx_t, s0,     r0, r1, r2, r3);
            load4idx(idx_t, s0 + 4, r4, r5, r6, r7);
            const float4 v0 = __ldg(w_t + r0 * D_VEC + lane);
            const float4 v1 = __ldg(w_t + r1 * D_VEC + lane);
            const float4 v2 = __ldg(w_t + r2 * D_VEC + lane);
            const float4 v3 = __ldg(w_t + r3 * D_VEC + lane);
            const float4 v4 = __ldg(w_t + r4 * D_VEC + lane);
            const float4 v5 = __ldg(w_t + r5 * D_VEC + lane);
            const float4 v6 = __ldg(w_t + r6 * D_VEC + lane);
            const float4 v7 = __ldg(w_t + r7 * D_VEC + lane);
            a0.x = (v0.x + v1.x) + (v2.x + v3.x);
            a0.y = (v0.y + v1.y) + (v2.y + v3.y);
            a0.z = (v0.z + v1.z) + (v2.z + v3.z);
            a0.w = (v0.w + v1.w) + (v2.w + v3.w);
            a1.x = (v4.x + v5.x) + (v6.x + v7.x);
            a1.y = (v4.y + v5.y) + (v6.y + v7.y);
            a1.z = (v4.z + v5.z) + (v6.z + v7.z);
            a1.w = (v4.w + v5.w) + (v6.w + v7.w);
        } else {
            a0 = pool_general(w_t, idx_t, s0, s1, lane);
            a1 = pool_general(w_t, idx_t, s1, e1, lane);
        }

        float4* o = out + (long long)bag0 * D_VEC + lane;
        store_cs(o, a0);
        store_cs(o + D_VEC, a1);
    }

    // Tail: odd total_bags -> last bag handled by warp 0.
    if ((total_bags & 1) && warp == 0) {
        const int bag = total_bags - 1;
        const int t = (bshift >= 0) ? (bag >> bshift) : (bag / B);
        const int b = bag - t * B;
        const IT* __restrict__ offs_t = offs + (long long)t * B;
        const long long s = (long long)offs_t[b];
        const long long e = (b + 1 < B) ? (long long)offs_t[b + 1] : (long long)BL;
        const float4 a = pool_general(w + (long long)t * wstride,
                                      idx + (long long)t * BL, s, e, lane);
        store_cs(out + (long long)bag * D_VEC + lane, a);
    }
}

__global__ void __launch_bounds__(256, 4)
embbag_sum_kernel(const float4* __restrict__ w,
                  const void* __restrict__ idx_raw,
                  const void* __restrict__ offs_raw,
                  float4* __restrict__ out,
                  int T, long long N, int B, int bshift, int BL)
{
    const int lane   = threadIdx.x & 31;
    const int warp   = (int)((blockIdx.x * blockDim.x + threadIdx.x) >> 5);
    const int nwarps = (int)((gridDim.x * blockDim.x) >> 5);
    const int total_bags = T * B;

    // In-kernel dtype detection (uniform load, L2 broadcast; see header).
    const bool is32 = (__ldg((const int*)offs_raw + 1) != 0);

    if (is32) {
        run_pairs<int>(w, (const int*)idx_raw, (const int*)offs_raw, out,
                       T, N, B, bshift, BL, total_bags, warp, nwarps, lane);
    } else {
        run_pairs<long long>(w, (const long long*)idx_raw, (const long long*)offs_raw, out,
                             T, N, B, bshift, BL, total_bags, warp, nwarps, lane);
    }
}

extern "C" void kernel_launch(void* const* d_in, const int* in_sizes, int n_in,
                              void* d_out, int out_size)
{
    const float4* weights = (const float4*)d_in[0];
    const void*   indices = d_in[1];
    const void*   offsets = d_in[2];
    float4*       out     = (float4*)d_out;

    const int T = 26;
    const int B  = in_sizes[2] / T;                                   // 16384
    const int BL = in_sizes[1] / T;                                   // 65536
    const long long N = (long long)in_sizes[0] / ((long long)T * D_DIM); // 100000

    int bshift = -1;
    if ((B & (B - 1)) == 0) {
        bshift = 0;
        while ((1 << bshift) != B) bshift++;
    }

    int sms = 148;
    cudaDeviceGetAttribute(&sms, cudaDevAttrMultiProcessorCount, 0);

    const int threads = 256;
    const int blocks  = sms * 8;   // persistent grid-stride

    embbag_sum_kernel<<<blocks, threads>>>(weights, indices, offsets, out,
                                           T, N, B, bshift, BL);
}

// round 6
// speedup vs baseline: 1.1041x; 1.1041x over previous
#include <cuda_runtime.h>
#include <stdint.h>

// MergedEmbSGD: merged multi-table EmbeddingBag, sum pooling.
// weights: [T, N, D] fp32 ; indices/offsets int32 or int64 (runtime-detected
// in-kernel: offsets per table = [0, L, 2L, ...]; int32 view of an int64
// buffer has elem 1 == 0, genuine int32 has elem 1 == L != 0).
// out: [T, B, D] fp32.
// One bag per warp, persistent grid-stride. R5 lesson: keep occupancy high and
// neighbor bags on concurrent warps so L2 dedups duplicate gathers.

#define D_DIM 128
#define D_VEC (D_DIM / 4)   // 32 float4 per row == one per lane

__device__ __forceinline__ void store_cs(float4* p, float4 v)
{
    asm volatile("st.global.cs.v4.f32 [%0], {%1,%2,%3,%4};"
                 :: "l"(p), "f"(v.x), "f"(v.y), "f"(v.z), "f"(v.w) : "memory");
}

// Load 4 consecutive indices starting at s (caller guarantees s % 4 == 0).
__device__ __forceinline__ void load4idx(const int* p, int s,
                                         int& r0, int& r1, int& r2, int& r3)
{
    int4 v = __ldg((const int4*)(p + s));
    r0 = v.x; r1 = v.y; r2 = v.z; r3 = v.w;
}
__device__ __forceinline__ void load4idx(const long long* p, int s,
                                         int& r0, int& r1, int& r2, int& r3)
{
    longlong2 a = __ldg((const longlong2*)(p + s));
    longlong2 b = __ldg((const longlong2*)(p + s + 2));
    r0 = (int)a.x; r1 = (int)a.y; r2 = (int)b.x; r3 = (int)b.y;
}

template <typename IT>
__device__ __forceinline__ void run_bags(
    const float4* __restrict__ w,
    const IT* __restrict__ idx,
    const IT* __restrict__ offs,
    float4* __restrict__ out,
    int T, long long N, int B, int bshift, int BL, int total_bags,
    int warp, int nwarps, int lane)
{
    const long long wstride = N * D_VEC;   // float4 per table

    for (int bag = warp; bag < total_bags; bag += nwarps) {
        const int t = (bshift >= 0) ? (bag >> bshift) : (bag / B);
        const int b = bag - t * B;

        const IT* __restrict__ offs_t = offs + (long long)t * B;
        const int start = (int)offs_t[b];
        const int end   = (b + 1 < B) ? (int)offs_t[b + 1] : BL;

        const IT*     __restrict__ idx_t = idx + (long long)t * BL;
        const float4* __restrict__ w_t   = w + (long long)t * wstride;

        float4 acc; acc.x = 0.f; acc.y = 0.f; acc.z = 0.f; acc.w = 0.f;
        const int n = end - start;

        if (n == 4 && ((start & 3) == 0)) {
            // Fast path: pooling factor 4. One index load, 4 row loads in flight.
            int r0, r1, r2, r3;
            load4idx(idx_t, start, r0, r1, r2, r3);
            const float4 v0 = __ldg(w_t + (long long)r0 * D_VEC + lane);
            const float4 v1 = __ldg(w_t + (long long)r1 * D_VEC + lane);
            const float4 v2 = __ldg(w_t + (long long)r2 * D_VEC + lane);
            const float4 v3 = __ldg(w_t + (long long)r3 * D_VEC + lane);
            acc.x = (v0.x + v1.x) + (v2.x + v3.x);
            acc.y = (v0.y + v1.y) + (v2.y + v3.y);
            acc.z = (v0.z + v1.z) + (v2.z + v3.z);
            acc.w = (v0.w + v1.w) + (v2.w + v3.w);
        } else {
            for (int i = start; i < end; ++i) {
                const long long r = (long long)idx_t[i];
                const float4 v = __ldg(w_t + r * D_VEC + lane);
                acc.x += v.x; acc.y += v.y; acc.z += v.z; acc.w += v.w;
            }
        }

        store_cs(out + (long long)bag * D_VEC + lane, acc);
    }
}

__global__ void __launch_bounds__(256, 8)
embbag_sum_kernel(const float4* __restrict__ w,
                  const void* __restrict__ idx_raw,
                  const void* __restrict__ offs_raw,
                  float4* __restrict__ out,
                  int T, long long N, int B, int bshift, int BL)
{
    const int lane   = threadIdx.x & 31;
    const int warp   = (int)((blockIdx.x * blockDim.x + threadIdx.x) >> 5);
    const int nwarps = (int)((gridDim.x * blockDim.x) >> 5);
    const int total_bags = T * B;

    // In-kernel dtype detection (uniform load, L2 broadcast; see header).
    const bool is32 = (__ldg((const int*)offs_raw + 1) != 0);

    if (is32) {
        run_bags<int>(w, (const int*)idx_raw, (const int*)offs_raw, out,
                      T, N, B, bshift, BL, total_bags, warp, nwarps, lane);
    } else {
        run_bags<long long>(w, (const long long*)idx_raw, (const long long*)offs_raw, out,
                            T, N, B, bshift, BL, total_bags, warp, nwarps, lane);
    }
}

extern "C" void kernel_launch(void* const* d_in, const int* in_sizes, int n_in,
                              void* d_out, int out_size)
{
    const float4* weights = (const float4*)d_in[0];
    const void*   indices = d_in[1];
    const void*   offsets = d_in[2];
    float4*       out     = (float4*)d_out;

    const int T = 26;
    const int B  = in_sizes[2] / T;                                   // 16384
    const int BL = in_sizes[1] / T;                                   // 65536
    const long long N = (long long)in_sizes[0] / ((long long)T * D_DIM); // 100000

    int bshift = -1;
    if ((B & (B - 1)) == 0) {
        bshift = 0;
        while ((1 << bshift) != B) bshift++;
    }

    int sms = 148;
    cudaDeviceGetAttribute(&sms, cudaDevAttrMultiProcessorCount, 0);

    const int threads = 256;
    const int blocks  = sms * 8;   // persistent: one full-occupancy wave

    embbag_sum_kernel<<<blocks, threads>>>(weights, indices, offsets, out,
                                           T, N, B, bshift, BL);
}

// round 8
// speedup vs baseline: 1.1117x; 1.0069x over previous
#include <cuda_runtime.h>
#include <stdint.h>

// MergedEmbSGD: merged multi-table EmbeddingBag, sum pooling.
// weights: [T, N, D] fp32 ; indices/offsets int32 or int64 (runtime-detected
// in-kernel: offsets per table = [0, L, 2L, ...]; int32 view of an int64
// buffer has elem 1 == 0, genuine int32 has elem 1 == L != 0).
// out: [T, B, D] fp32.
// One bag per warp, persistent grid-stride (R4 structure — proven best).
// Weight gathers carry an L2 evict-last cache hint (createpolicy form —
// inline qualifier is illegal on 128-bit loads for sm_103a ptxas) so the
// ~27% duplicate rows survive in L2; output uses st.cs (evict-first).

#define D_DIM 128
#define D_VEC (D_DIM / 4)   // 32 float4 per row == one per lane

__device__ __forceinline__ void store_cs(float4* p, float4 v)
{
    asm volatile("st.global.cs.v4.f32 [%0], {%1,%2,%3,%4};"
                 :: "l"(p), "f"(v.x), "f"(v.y), "f"(v.z), "f"(v.w) : "memory");
}

__device__ __forceinline__ unsigned long long make_evict_last_policy()
{
    unsigned long long pol;
    asm("createpolicy.fractional.L2::evict_last.b64 %0, 1.0;" : "=l"(pol));
    return pol;
}

// Weight-row gather: read-only, L2 evict-last via cache-hint policy.
__device__ __forceinline__ float4 ldg_el(const float4* p, unsigned long long pol)
{
    float4 v;
    asm volatile("ld.global.nc.L2::cache_hint.v4.f32 {%0,%1,%2,%3}, [%4], %5;"
                 : "=f"(v.x), "=f"(v.y), "=f"(v.z), "=f"(v.w)
                 : "l"(p), "l"(pol));
    return v;
}

// Load 4 consecutive indices starting at s (caller guarantees s % 4 == 0).
__device__ __forceinline__ void load4idx(const int* p, long long s,
                                         long long& r0, long long& r1,
                                         long long& r2, long long& r3)
{
    int4 v = __ldg((const int4*)(p + s));
    r0 = v.x; r1 = v.y; r2 = v.z; r3 = v.w;
}
__device__ __forceinline__ void load4idx(const long long* p, long long s,
                                         long long& r0, long long& r1,
                                         long long& r2, long long& r3)
{
    longlong2 a = __ldg((const longlong2*)(p + s));
    longlong2 b = __ldg((const longlong2*)(p + s + 2));
    r0 = a.x; r1 = a.y; r2 = b.x; r3 = b.y;
}

template <typename IT>
__device__ __forceinline__ void run_bags(
    const float4* __restrict__ w,
    const IT* __restrict__ idx,
    const IT* __restrict__ offs,
    float4* __restrict__ out,
    int T, long long N, int B, int bshift, int BL, int total_bags,
    int warp, int nwarps, int lane)
{
    const long long wstride = N * D_VEC;   // float4 per table
    const unsigned long long pol = make_evict_last_policy();

    for (int bag = warp; bag < total_bags; bag += nwarps) {
        const int t = (bshift >= 0) ? (bag >> bshift) : (bag / B);
        const int b = bag - t * B;

        const IT* __restrict__ offs_t = offs + (long long)t * B;
        const long long start = (long long)offs_t[b];
        const long long end   = (b + 1 < B) ? (long long)offs_t[b + 1]
                                            : (long long)BL;

        const IT*     __restrict__ idx_t = idx + (long long)t * BL;
        const float4* __restrict__ w_t   = w + (long long)t * wstride;

        float4 acc; acc.x = 0.f; acc.y = 0.f; acc.z = 0.f; acc.w = 0.f;
        const long long n = end - start;

        if (n == 4 && ((start & 3) == 0)) {
            // Fast path: pooling factor 4. One index load, 4 row loads in flight.
            long long r0, r1, r2, r3;
            load4idx(idx_t, start, r0, r1, r2, r3);
            const float4 v0 = ldg_el(w_t + r0 * D_VEC + lane, pol);
            const float4 v1 = ldg_el(w_t + r1 * D_VEC + lane, pol);
            const float4 v2 = ldg_el(w_t + r2 * D_VEC + lane, pol);
            const float4 v3 = ldg_el(w_t + r3 * D_VEC + lane, pol);
            acc.x = (v0.x + v1.x) + (v2.x + v3.x);
            acc.y = (v0.y + v1.y) + (v2.y + v3.y);
            acc.z = (v0.z + v1.z) + (v2.z + v3.z);
            acc.w = (v0.w + v1.w) + (v2.w + v3.w);
        } else {
            for (long long i = start; i < end; ++i) {
                const long long r = (long long)idx_t[i];
                const float4 v = ldg_el(w_t + r * D_VEC + lane, pol);
                acc.x += v.x; acc.y += v.y; acc.z += v.z; acc.w += v.w;
            }
        }

        store_cs(out + (long long)bag * D_VEC + lane, acc);
    }
}

__global__ void __launch_bounds__(256, 8)
embbag_sum_kernel(const float4* __restrict__ w,
                  const void* __restrict__ idx_raw,
                  const void* __restrict__ offs_raw,
                  float4* __restrict__ out,
                  int T, long long N, int B, int bshift, int BL)
{
    const int lane   = threadIdx.x & 31;
    const int warp   = (int)((blockIdx.x * blockDim.x + threadIdx.x) >> 5);
    const int nwarps = (int)((gridDim.x * blockDim.x) >> 5);
    const int total_bags = T * B;

    // In-kernel dtype detection (uniform load, L2 broadcast; see header).
    const bool is32 = (__ldg((const int*)offs_raw + 1) != 0);

    if (is32) {
        run_bags<int>(w, (const int*)idx_raw, (const int*)offs_raw, out,
                      T, N, B, bshift, BL, total_bags, warp, nwarps, lane);
    } else {
        run_bags<long long>(w, (const long long*)idx_raw, (const long long*)offs_raw, out,
                            T, N, B, bshift, BL, total_bags, warp, nwarps, lane);
    }
}

extern "C" void kernel_launch(void* const* d_in, const int* in_sizes, int n_in,
                              void* d_out, int out_size)
{
    const float4* weights = (const float4*)d_in[0];
    const void*   indices = d_in[1];
    const void*   offsets = d_in[2];
    float4*       out     = (float4*)d_out;

    const int T = 26;
    const int B  = in_sizes[2] / T;                                   // 16384
    const int BL = in_sizes[1] / T;                                   // 65536
    const long long N = (long long)in_sizes[0] / ((long long)T * D_DIM); // 100000

    int bshift = -1;
    if ((B & (B - 1)) == 0) {
        bshift = 0;
        while ((1 << bshift) != B) bshift++;
    }

    int sms = 148;
    cudaDeviceGetAttribute(&sms, cudaDevAttrMultiProcessorCount, 0);

    const int threads = 256;
    const int blocks  = sms * 8;   // persistent: one full-occupancy wave

    embbag_sum_kernel<<<blocks, threads>>>(weights, indices, offsets, out,
                                           T, N, B, bshift, BL);
}